// round 14
// baseline (speedup 1.0000x reference)
#include <cuda_runtime.h>
#include <cuda_fp16.h>
#include <cstdint>

// ---------------- problem constants ----------------
#define Bn   32
#define Tn   3000
#define Cn   512
#define KKn  2560
#define KP   (KKn/2)              // packed fp16-pair words per co
#define BTn  (Bn*Tn)
#define CS_SZ   (BTn*Cn)
#define MASK_OFF CS_SZ
#define LOSS_OFF (CS_SZ + BTn)

#define NB 4                      // co blocks of 128
#define NCH 80                    // K-chunks of 32
#define RW 20                     // words per smem row (16 data + 4 pad)
// stage (words): A1[128][20] @0, A2 @2560, B1 @5120, B2 @7680
#define STG_W 10240
#define SMEM_BYTES (2*STG_W*4)    // 81920

// ---------------- scratch ----------------
__device__ uint32_t g_wh1[(size_t)Cn*KP];     // weight fp16 plane 1 [co][kw]
__device__ uint32_t g_wh2[(size_t)Cn*KP];     // plane 2 (residual)
__device__ uint32_t g_ah1[(size_t)Bn*Tn*256]; // hs fp16 plane 1 [b][t][ciw]
__device__ uint32_t g_ah2[(size_t)Bn*Tn*256]; // plane 2
__device__ float g_part[NB*BTn];
__device__ float g_alpha[BTn];
__device__ float g_w1[BTn];
__device__ float g_w2[BTn];
__device__ int   g_fpos[BTn];
__device__ int   g_nfire[Bn];
__device__ int   g_tail[Bn];
__device__ float g_bsum[Bn];

// ---------------- helpers ----------------
__device__ __forceinline__ uint32_t smem_u32(const void* p) {
    uint32_t a;
    asm("{ .reg .u64 t; cvta.to.shared.u64 t, %1; cvt.u32.u64 %0, t; }"
        : "=r"(a) : "l"(p));
    return a;
}
__device__ __forceinline__ void cp16(uint32_t dst, const void* src) {
    asm volatile("cp.async.cg.shared.global [%0], [%1], 16;"
                 :: "r"(dst), "l"(src));
}
__device__ __forceinline__ void cp16z(uint32_t dst, const void* src, uint32_t sz) {
    asm volatile("cp.async.cg.shared.global [%0], [%1], 16, %2;"
                 :: "r"(dst), "l"(src), "r"(sz));
}
__device__ __forceinline__ void mma16(float* c, const uint32_t* a,
                                      const uint32_t* b) {
    asm volatile(
        "mma.sync.aligned.m16n8k16.row.col.f32.f16.f16.f32 "
        "{%0,%1,%2,%3}, {%4,%5,%6,%7}, {%8,%9}, {%0,%1,%2,%3};"
        : "+f"(c[0]), "+f"(c[1]), "+f"(c[2]), "+f"(c[3])
        : "r"(a[0]), "r"(a[1]), "r"(a[2]), "r"(a[3]), "r"(b[0]), "r"(b[1]));
}
__device__ __forceinline__ void ldsm4(uint32_t* r, uint32_t addr) {
    asm volatile("ldmatrix.sync.aligned.m8n8.x4.shared.b16 {%0,%1,%2,%3}, [%4];"
                 : "=r"(r[0]), "=r"(r[1]), "=r"(r[2]), "=r"(r[3])
                 : "r"(addr));
}
// 2-way fp16 split of a float pair (even in low half).
__device__ __forceinline__ void hsplit2(float xe, float xo, uint32_t& P1,
                                        uint32_t& P2) {
    __half2 h1 = __floats2half2_rn(xe, xo);
    float2 b = __half22float2(h1);
    __half2 h2 = __floats2half2_rn(xe - b.x, xo - b.y);
    P1 = *reinterpret_cast<uint32_t*>(&h1);
    P2 = *reinterpret_cast<uint32_t*>(&h2);
}

// ---------------- 0a) weights -> 2 packed fp16 planes, K reordered ----------
__global__ void prep_w_k(const float* __restrict__ cw) {
    int idx = blockIdx.x * blockDim.x + threadIdx.x;
    if (idx >= Cn * 256) return;
    int co = idx >> 8;
    int cp = idx & 255;
    const float* p = cw + (size_t)co * KKn + cp * 10;
#pragma unroll
    for (int kr = 0; kr < 5; kr++) {
        uint32_t P1, P2;
        hsplit2(p[kr], p[5 + kr], P1, P2);
        size_t o = (size_t)co * KP + kr * 256 + cp;
        g_wh1[o] = P1;
        g_wh2[o] = P2;
    }
}

// ---------------- 0b) hs -> 2 packed fp16 planes [b][t][ciw] -----------------
__global__ void prep_a_k(const float* __restrict__ hs) {
    size_t idx = (size_t)blockIdx.x * blockDim.x + threadIdx.x;
    if (idx >= (size_t)Bn * Tn * 64) return;
    const float4* src = reinterpret_cast<const float4*>(hs) + idx * 2;
    float4 x0 = src[0], x1 = src[1];
    uint32_t p1[4], p2[4];
    hsplit2(x0.x, x0.y, p1[0], p2[0]);
    hsplit2(x0.z, x0.w, p1[1], p2[1]);
    hsplit2(x1.x, x1.y, p1[2], p2[2]);
    hsplit2(x1.z, x1.w, p1[3], p2[3]);
    reinterpret_cast<uint4*>(g_ah1)[idx] = make_uint4(p1[0], p1[1], p1[2], p1[3]);
    reinterpret_cast<uint4*>(g_ah2)[idx] = make_uint4(p2[0], p2[1], p2[2], p2[3]);
}

// ---------------- dummy (position conv at profiled launch index) ------------
__global__ void dummy1_k() { if (threadIdx.x < Bn) g_bsum[threadIdx.x] = 0.f; }

// ---------------- 1) conv GEMM: 512 threads, warp 32t x 32co ----------------
__global__ void __launch_bounds__(512, 1)
conv_mma_k(const float* __restrict__ convb, const float* __restrict__ linw) {
    extern __shared__ float S[];
    const int tid  = threadIdx.x;
    const int wid  = tid >> 5, lane = tid & 31;
    const int g    = lane >> 2, q = lane & 3;
    const int wm   = wid & 3,  wn = wid >> 2;        // wn in 0..3
    const int cb   = blockIdx.x;
    const int tile = blockIdx.y;
    const int b    = tile / 24;
    const int tt0  = (tile % 24) * 128;
    const int co0  = cb * 128;
    const uint32_t sm0 = smem_u32(S);

    // fill roles: 1 thread per (plane,row): pl = tid>>7, row = tid&127
    const int plF = tid >> 7;
    const int rF  = tid & 127;
    const uint32_t* bsrcW =
        (plF == 2 ? g_wh1 : g_wh2) + (size_t)(co0 + rF) * KP;

    // ldmatrix per-lane base addresses (bytes), stride RW=20 words
    const uint32_t aRow = wm * 32 + (lane & 7) + ((lane >> 3) & 1) * 8;
    const uint32_t aWord = (lane >> 4) * 4;
    const uint32_t bRow = wn * 32 + (lane & 7) + (lane >> 4) * 8;
    const uint32_t bWord = ((lane >> 3) & 1) * 4;
    const uint32_t aBase = sm0 + (aRow * RW + aWord) * 4;
    const uint32_t bBase = sm0 + (5120 + bRow * RW + bWord) * 4;

    float acc[2][4][4];
    float msum[2][4][4];
#pragma unroll
    for (int i = 0; i < 2; i++)
#pragma unroll
        for (int j = 0; j < 4; j++)
#pragma unroll
            for (int e = 0; e < 4; e++) { acc[i][j][e] = 0.f; msum[i][j][e] = 0.f; }

    // ---- fill macro: chunk c into stage s (1 row of 16 words per thread) ---
#define FILL_CHUNK(c_, s_)                                                     \
    {                                                                          \
        const int kb_  = (c_) * 32;                                            \
        uint32_t dst_ = sm0 + ((s_) * STG_W + plF * 2560 + rF * RW) * 4;       \
        if (plF < 2) {                                                         \
            const int kr_  = kb_ >> 9;                                         \
            const int ciw_ = (kb_ & 511) >> 1;                                 \
            int tsrc_ = tt0 + rF + kr_ - 2;                                    \
            bool v_ = ((unsigned)tsrc_ < (unsigned)Tn);                        \
            uint32_t sz_ = v_ ? 16u : 0u;                                      \
            const uint32_t* a_ = (plF == 0 ? g_ah1 : g_ah2) +                  \
                ((size_t)b * Tn + (v_ ? tsrc_ : 0)) * 256 + ciw_;              \
            cp16z(dst_,      a_,      sz_);                                    \
            cp16z(dst_ + 16, a_ + 4,  sz_);                                    \
            cp16z(dst_ + 32, a_ + 8,  sz_);                                    \
            cp16z(dst_ + 48, a_ + 12, sz_);                                    \
        } else {                                                               \
            const uint32_t* w_ = bsrcW + (c_) * 16;                            \
            cp16(dst_,      w_);                                               \
            cp16(dst_ + 16, w_ + 4);                                           \
            cp16(dst_ + 32, w_ + 8);                                           \
            cp16(dst_ + 48, w_ + 12);                                          \
        }                                                                      \
        asm volatile("cp.async.commit_group;" ::: "memory");                   \
    }

    FILL_CHUNK(0, 0);
    asm volatile("cp.async.wait_group 0;" ::: "memory");
    __syncthreads();

    for (int c = 0; c < NCH; c++) {
        const int st  = c & 1;
        const int nst = st ^ 1;
        const bool more = (c + 1 < NCH);

        if (more) FILL_CHUNK(c + 1, nst);

        // ---- compute: 3 split terms, 2 k-steps of K=16 ----
        const uint32_t stoff = (uint32_t)st * STG_W * 4;
#pragma unroll
        for (int ks = 0; ks < 2; ks++) {
            const uint32_t kso = ks * 32;
            uint32_t A1[2][4], A2[2][4];
#pragma unroll
            for (int mf = 0; mf < 2; mf++) {
                ldsm4(A1[mf], aBase + stoff + mf * (16 * RW * 4) + kso);
                ldsm4(A2[mf], aBase + stoff + 2560 * 4 + mf * (16 * RW * 4) + kso);
            }
            uint32_t B1f[2][4];
#pragma unroll
            for (int nfp = 0; nfp < 2; nfp++)
                ldsm4(B1f[nfp], bBase + stoff + nfp * (16 * RW * 4) + kso);
#pragma unroll
            for (int mf = 0; mf < 2; mf++)
#pragma unroll
                for (int nf = 0; nf < 4; nf++) {
                    const uint32_t* bf = &B1f[nf >> 1][(nf & 1) * 2];
                    mma16(acc[mf][nf], A1[mf], bf);
                    mma16(acc[mf][nf], A2[mf], bf);
                }
            uint32_t B2f[2][4];
#pragma unroll
            for (int nfp = 0; nfp < 2; nfp++)
                ldsm4(B2f[nfp], bBase + stoff + 2560 * 4 + nfp * (16 * RW * 4) + kso);
#pragma unroll
            for (int mf = 0; mf < 2; mf++)
#pragma unroll
                for (int nf = 0; nf < 4; nf++) {
                    const uint32_t* bf = &B2f[nf >> 1][(nf & 1) * 2];
                    mma16(acc[mf][nf], A1[mf], bf);
                }
        }

        // ---- grouped drain every 4 chunks (128 K) ----
        if ((c & 3) == 3) {
#pragma unroll
            for (int mf = 0; mf < 2; mf++)
#pragma unroll
                for (int nf = 0; nf < 4; nf++)
#pragma unroll
                    for (int e = 0; e < 4; e++) {
                        msum[mf][nf][e] += acc[mf][nf][e];
                        acc[mf][nf][e] = 0.f;
                    }
        }

        if (more)
            asm volatile("cp.async.wait_group 0;" ::: "memory");
        __syncthreads();
    }
#undef FILL_CHUNK

    // ---- epilogue: relu(x+bias)*lin_w, reduce over this CTA's 128 co ----
    float bias_v[4][2], lw_v[4][2];
#pragma unroll
    for (int nf = 0; nf < 4; nf++)
#pragma unroll
        for (int e = 0; e < 2; e++) {
            int cg = co0 + wn * 32 + nf * 8 + 2 * q + e;
            bias_v[nf][e] = convb[cg];
            lw_v[nf][e]   = linw[cg];
        }
    float* red = S;                              // 4 x 128 floats
#pragma unroll
    for (int mf = 0; mf < 2; mf++) {
#pragma unroll
        for (int h = 0; h < 2; h++) {
            float s = 0.f;
#pragma unroll
            for (int nf = 0; nf < 4; nf++)
#pragma unroll
                for (int e = 0; e < 2; e++) {
                    float xv = msum[mf][nf][h * 2 + e] + bias_v[nf][e];
                    xv = fmaxf(xv, 0.f);
                    s = fmaf(lw_v[nf][e], xv, s);
                }
            s += __shfl_xor_sync(0xffffffffu, s, 1);
            s += __shfl_xor_sync(0xffffffffu, s, 2);
            if (q == 0)
                red[wn * 128 + wm * 32 + mf * 16 + h * 8 + g] = s;
        }
    }
    __syncthreads();
    if (tid < 128) {
        float v = red[tid] + red[128 + tid] + red[256 + tid] + red[384 + tid];
        int t = tt0 + tid;
        if (t < Tn) g_part[cb * BTn + b * Tn + t] = v;
    }
}

// ---------------- 2) alpha = sigmoid(fp64 sum of 4 partials + lin_b) --------
__global__ void alpha_k(const float* __restrict__ linb) {
    int idx = blockIdx.x * blockDim.x + threadIdx.x;
    if (idx >= BTn) return;
    double l = (double)linb[0];
#pragma unroll
    for (int p = 0; p < NB; p++) l += (double)g_part[p * BTn + idx];
    float lf = (float)l;
    g_alpha[idx] = 1.0f / (1.0f + expf(-lf));
}

// ---------------- 3) loss ----------------------------------------------------
__global__ void loss_a_k() {
    int b = blockIdx.x;
    __shared__ float sm[256];
    float s = 0.f;
    for (int t = threadIdx.x; t < Tn; t += 256) s += g_alpha[b * Tn + t];
    sm[threadIdx.x] = s;
    __syncthreads();
    for (int st = 128; st > 0; st >>= 1) {
        if (threadIdx.x < st) sm[threadIdx.x] += sm[threadIdx.x + st];
        __syncthreads();
    }
    if (threadIdx.x == 0) g_bsum[b] = sm[0];
}
__global__ void loss_b_k(float* out, int out_size) {
    if ((long long)out_size > LOSS_OFF) {
        float s = 0.f;
        for (int b = 0; b < Bn; b++) s += fabsf(g_bsum[b]);
        out[LOSS_OFF] = s;
    }
}

// ---------------- 4) scalar CIF scan (one warp per sequence) ----------------
__global__ void scan_k(const int* __restrict__ msk) {
    int b = blockIdx.x;
    int lane = threadIdx.x;
    float acc = 0.0f;
    int nfire = 0;
    for (int t0 = 0; t0 < Tn; t0 += 32) {
        int t = t0 + lane;
        float a = 0.f;
        if (t < Tn) {
            a = g_alpha[b * Tn + t];
            if (msk[b * Tn + t] == 0) a = 0.f;
        }
        int n = min(32, Tn - t0);
        float w1 = 0.f, w2 = 0.f;
        for (int i = 0; i < n; i++) {
            float ai = __shfl_sync(0xffffffffu, a, i);
            float acc2 = acc + ai;
            bool fired = (acc2 >= 1.0f);
            float a1 = 1.0f - acc;
            if (lane == i) {
                if (fired) { w1 = a1; w2 = ai - a1; }
                else       { w1 = ai; w2 = 0.f; }
            }
            if (fired) {
                if (lane == i) g_fpos[b * Tn + nfire] = t0 + i;
                nfire++;
                acc = ai - a1;
            } else {
                acc = acc2;
            }
        }
        if (t < Tn) { g_w1[b * Tn + t] = w1; g_w2[b * Tn + t] = w2; }
    }
    if (lane == 0) {
        g_nfire[b] = nfire;
        g_tail[b]  = (acc >= 0.5f) ? 1 : 0;
    }
}

// ---------------- 5) parallel emission ---------------------------------------
__global__ void emit_k(const float* __restrict__ hs, float* __restrict__ out,
                       int out_size) {
    int row = blockIdx.x;
    int b = row / Tn;
    int j = row % Tn;
    int nf = g_nfire[b];
    int nr = nf + g_tail[b];
    float4 accv = make_float4(0.f, 0.f, 0.f, 0.f);
    int c4 = threadIdx.x;
    const float4* hb = reinterpret_cast<const float4*>(hs) + (size_t)b * Tn * 128;
    if (j < nr) {
        int s = (j == 0) ? 0 : g_fpos[b * Tn + j - 1];
        int e = (j < nf) ? g_fpos[b * Tn + j] : (Tn - 1);
        for (int t = s; t <= e; t++) {
            float w = (t == s && j > 0) ? g_w2[b * Tn + t] : g_w1[b * Tn + t];
            float4 h = hb[(size_t)t * 128 + c4];
            accv.x = fmaf(w, h.x, accv.x);
            accv.y = fmaf(w, h.y, accv.y);
            accv.z = fmaf(w, h.z, accv.z);
            accv.w = fmaf(w, h.w, accv.w);
        }
    }
    reinterpret_cast<float4*>(out)[(size_t)row * 128 + c4] = accv;

    int nz = (accv.x != 0.f) | (accv.y != 0.f) | (accv.z != 0.f) | (accv.w != 0.f);
    __shared__ int s_any[4];
    unsigned bal = __ballot_sync(0xffffffffu, nz);
    if ((threadIdx.x & 31) == 0) s_any[threadIdx.x >> 5] = (bal != 0u);
    __syncthreads();
    if (threadIdx.x == 0) {
        int any = s_any[0] | s_any[1] | s_any[2] | s_any[3];
        if ((long long)out_size >= (long long)MASK_OFF + BTn)
            out[MASK_OFF + row] = any ? 1.0f : 0.0f;
    }
}

// ---------------- launcher ----------------------------------------------------
extern "C" void kernel_launch(void* const* d_in, const int* in_sizes, int n_in,
                              void* d_out, int out_size) {
    const float* hs  = (const float*)d_in[0];
    const int*   msk = (const int*)  d_in[1];
    const float* cw  = (const float*)d_in[2];
    const float* cb  = (const float*)d_in[3];
    const float* lw  = (const float*)d_in[4];
    const float* lb  = (const float*)d_in[5];
    float* out = (float*)d_out;

    cudaFuncSetAttribute(conv_mma_k, cudaFuncAttributeMaxDynamicSharedMemorySize,
                         SMEM_BYTES);

    prep_w_k<<<(Cn * 256 + 255) / 256, 256>>>(cw);
    prep_a_k<<<(Bn * Tn * 64 + 255) / 256, 256>>>(hs);
    dummy1_k<<<1, 32>>>();                       // conv stays at profiled slot 4
    conv_mma_k<<<dim3(NB, 768), 512, SMEM_BYTES>>>(cb, lw);
    alpha_k<<<(BTn + 255) / 256, 256>>>(lb);
    loss_a_k<<<Bn, 256>>>();
    loss_b_k<<<1, 1>>>(out, out_size);
    scan_k<<<Bn, 32>>>(msk);
    emit_k<<<BTn, 128>>>(hs, out, out_size);
}

// round 15
// speedup vs baseline: 1.2485x; 1.2485x over previous
#include <cuda_runtime.h>
#include <cuda_fp16.h>
#include <cstdint>

// ---------------- problem constants ----------------
#define Bn   32
#define Tn   3000
#define Cn   512
#define KKn  2560                 // Cin * ksize
#define KP   (KKn/2)              // packed fp16-pair words per co
#define BTn  (Bn*Tn)              // 96000
#define CS_SZ   (BTn*Cn)
#define MASK_OFF CS_SZ
#define LOSS_OFF (CS_SZ + BTn)

#define NB 4                      // co blocks of 128
#define NCH 80                    // K-chunks of 32
#define RW 20                     // words per smem row (16 data + 4 pad)
#define A_S(s) ((s)*2560)
#define B_S(s) (5120 + (s)*2560)
#define STG_W 10240
#define SMEM_BYTES (2*STG_W*4)    // 81920

// ---------------- scratch ----------------
__device__ uint32_t g_wh1[(size_t)Cn*KP];
__device__ uint32_t g_wh2[(size_t)Cn*KP];
__device__ float g_part[NB*BTn];
__device__ float g_alpha[BTn];
__device__ float g_w1[BTn];
__device__ float g_w2[BTn];
__device__ int   g_fpos[BTn];
__device__ int   g_nfire[Bn];
__device__ int   g_tail[Bn];
__device__ float g_bsum[Bn];

// ---------------- helpers ----------------
__device__ __forceinline__ uint32_t smem_u32(const void* p) {
    uint32_t a;
    asm("{ .reg .u64 t; cvta.to.shared.u64 t, %1; cvt.u32.u64 %0, t; }"
        : "=r"(a) : "l"(p));
    return a;
}
__device__ __forceinline__ void cp16(uint32_t dst, const void* src) {
    asm volatile("cp.async.cg.shared.global [%0], [%1], 16;"
                 :: "r"(dst), "l"(src));
}
__device__ __forceinline__ void mma16(float* c, const uint32_t* a,
                                      const uint32_t* b) {
    asm volatile(
        "mma.sync.aligned.m16n8k16.row.col.f32.f16.f16.f32 "
        "{%0,%1,%2,%3}, {%4,%5,%6,%7}, {%8,%9}, {%0,%1,%2,%3};"
        : "+f"(c[0]), "+f"(c[1]), "+f"(c[2]), "+f"(c[3])
        : "r"(a[0]), "r"(a[1]), "r"(a[2]), "r"(a[3]), "r"(b[0]), "r"(b[1]));
}
__device__ __forceinline__ void ldsm4(uint32_t* r, uint32_t addr) {
    asm volatile("ldmatrix.sync.aligned.m8n8.x4.shared.b16 {%0,%1,%2,%3}, [%4];"
                 : "=r"(r[0]), "=r"(r[1]), "=r"(r[2]), "=r"(r[3])
                 : "r"(addr));
}
// 2-way fp16 split of a float pair (even in low half).
__device__ __forceinline__ void hsplit2(float xe, float xo, uint32_t& P1,
                                        uint32_t& P2) {
    __half2 h1 = __floats2half2_rn(xe, xo);
    float2 b = __half22float2(h1);
    __half2 h2 = __floats2half2_rn(xe - b.x, xo - b.y);
    P1 = *reinterpret_cast<uint32_t*>(&h1);
    P2 = *reinterpret_cast<uint32_t*>(&h2);
}

// ---------------- 0) weights -> 2 packed fp16 planes, K reordered -----------
__global__ void prep_w_k(const float* __restrict__ cw) {
    int idx = blockIdx.x * blockDim.x + threadIdx.x;
    if (idx >= Cn * 256) return;
    int co = idx >> 8;
    int cp = idx & 255;
    const float* p = cw + (size_t)co * KKn + cp * 10;
#pragma unroll
    for (int kr = 0; kr < 5; kr++) {
        uint32_t P1, P2;
        hsplit2(p[kr], p[5 + kr], P1, P2);
        size_t o = (size_t)co * KP + kr * 256 + cp;
        g_wh1[o] = P1;
        g_wh2[o] = P2;
    }
}

// ---------------- dummies (position conv at profiled launch index) ----------
__global__ void dummy1_k() { if (threadIdx.x < Bn) g_bsum[threadIdx.x] = 0.f; }
__global__ void dummy2_k() {}

// ---------------- 1) conv GEMM: fp16 3-term split, whole-chunk frag preload -
// CTA 128t x 128co. 8 warps: wm=wid&3 (32 t), wn=wid>>2 (64 co). 1 CTA/SM.
__global__ void __launch_bounds__(256, 1)
conv_mma_k(const float* __restrict__ hs, const float* __restrict__ convb,
           const float* __restrict__ linw) {
    extern __shared__ float S[];
    const int tid  = threadIdx.x;
    const int wid  = tid >> 5, lane = tid & 31;
    const int g    = lane >> 2, q = lane & 3;
    const int wm   = wid & 3,  wn = wid >> 2;
    const int cb   = blockIdx.x;
    const int tile = blockIdx.y;
    const int b    = tile / 24;
    const int tt0  = (tile % 24) * 128;
    const int co0  = cb * 128;
    const uint32_t sm0 = smem_u32(S);

    // fill roles
    const int rA  = tid >> 1, hA = tid & 1;
    const int rB  = tid >> 1, hB = (tid & 1) * 8;
    const uint32_t* wsrc1 = g_wh1 + (size_t)(co0 + rB) * KP + hB;
    const uint32_t* wsrc2 = g_wh2 + (size_t)(co0 + rB) * KP + hB;

    // ldmatrix per-lane base addresses (bytes)
    const uint32_t aRow = wm * 32 + (lane & 7) + ((lane >> 3) & 1) * 8;
    const uint32_t aWord = (lane >> 4) * 4;
    const uint32_t bRow = wn * 64 + (lane & 7) + (lane >> 4) * 8;
    const uint32_t bWord = ((lane >> 3) & 1) * 4;
    const uint32_t aBase = sm0 + (A_S(0) + aRow * RW + aWord) * 4;
    const uint32_t bBase = sm0 + (B_S(0) + bRow * RW + bWord) * 4;

    float acc[2][8][4];
    float msum[2][8][4];
#pragma unroll
    for (int i = 0; i < 2; i++)
#pragma unroll
        for (int j = 0; j < 8; j++)
#pragma unroll
            for (int e = 0; e < 4; e++) { acc[i][j][e] = 0.f; msum[i][j][e] = 0.f; }

    // ---- prime stage 0 ----
    {
        cp16(sm0 + (B_S(0) + rB * RW + hB) * 4, wsrc1);
        cp16(sm0 + (B_S(0) + rB * RW + hB + 4) * 4, wsrc1 + 4);
        cp16(sm0 + (B_S(1) + rB * RW + hB) * 4, wsrc2);
        cp16(sm0 + (B_S(1) + rB * RW + hB + 4) * 4, wsrc2 + 4);
        asm volatile("cp.async.commit_group;" ::: "memory");

        int tsrc = tt0 + rA - 2;
        bool v = ((unsigned)tsrc < (unsigned)Tn);
        const float* src = hs + ((size_t)b * Tn + tsrc) * Cn + hA * 16;
        float4 x[4];
#pragma unroll
        for (int j = 0; j < 4; j++)
            x[j] = v ? reinterpret_cast<const float4*>(src)[j]
                     : make_float4(0.f, 0.f, 0.f, 0.f);
        uint32_t p1[8], p2[8];
        const float* xs = reinterpret_cast<const float*>(x);
#pragma unroll
        for (int j = 0; j < 8; j++)
            hsplit2(xs[2 * j], xs[2 * j + 1], p1[j], p2[j]);
        uint4* d1 = reinterpret_cast<uint4*>(&S[A_S(0) + rA * RW + hA * 8]);
        uint4* d2 = reinterpret_cast<uint4*>(&S[A_S(1) + rA * RW + hA * 8]);
        d1[0] = make_uint4(p1[0], p1[1], p1[2], p1[3]);
        d1[1] = make_uint4(p1[4], p1[5], p1[6], p1[7]);
        d2[0] = make_uint4(p2[0], p2[1], p2[2], p2[3]);
        d2[1] = make_uint4(p2[4], p2[5], p2[6], p2[7]);
        asm volatile("cp.async.wait_group 0;" ::: "memory");
    }
    __syncthreads();

    for (int c = 0; c < NCH; c++) {
        const int st  = c & 1;
        const int nst = st ^ 1;
        const bool more = (c + 1 < NCH);

        float4 x[4];
        if (more) {
            const int kb1 = (c + 1) * 32;
            const int kw1 = kb1 >> 1;
            const uint32_t base = sm0 + nst * STG_W * 4;
            cp16(base + (B_S(0) + rB * RW + hB) * 4, wsrc1 + kw1);
            cp16(base + (B_S(0) + rB * RW + hB + 4) * 4, wsrc1 + kw1 + 4);
            cp16(base + (B_S(1) + rB * RW + hB) * 4, wsrc2 + kw1);
            cp16(base + (B_S(1) + rB * RW + hB + 4) * 4, wsrc2 + kw1 + 4);
            asm volatile("cp.async.commit_group;" ::: "memory");
            const int kr = kb1 >> 9, ci = kb1 & 511;
            int tsrc = tt0 + rA + kr - 2;
            bool v = ((unsigned)tsrc < (unsigned)Tn);
            const float* src = hs + ((size_t)b * Tn + tsrc) * Cn + ci + hA * 16;
#pragma unroll
            for (int j = 0; j < 4; j++)
                x[j] = v ? reinterpret_cast<const float4*>(src)[j]
                         : make_float4(0.f, 0.f, 0.f, 0.f);
        }

        // ---- preload ALL fragments for both ks-steps, then all mma ----
        const uint32_t stoff = (uint32_t)st * STG_W * 4;
        uint32_t A1[2][2][4], A2[2][2][4];      // [ks][mf]
        uint32_t B1f[2][4][4], B2f[2][4][4];    // [ks][nfp]
#pragma unroll
        for (int ks = 0; ks < 2; ks++) {
            const uint32_t kso = ks * 32;
#pragma unroll
            for (int mf = 0; mf < 2; mf++) {
                ldsm4(A1[ks][mf], aBase + stoff + mf * (16 * RW * 4) + kso);
                ldsm4(A2[ks][mf], aBase + stoff + 10240 + mf * (16 * RW * 4) + kso);
            }
#pragma unroll
            for (int nfp = 0; nfp < 4; nfp++) {
                ldsm4(B1f[ks][nfp], bBase + stoff + nfp * (16 * RW * 4) + kso);
                ldsm4(B2f[ks][nfp], bBase + stoff + 10240 + nfp * (16 * RW * 4) + kso);
            }
        }
#pragma unroll
        for (int ks = 0; ks < 2; ks++) {
            // B1: A1xB1 + A2xB1 (same per-acc order as R12)
#pragma unroll
            for (int mf = 0; mf < 2; mf++)
#pragma unroll
                for (int nf = 0; nf < 8; nf++) {
                    const uint32_t* bf = &B1f[ks][nf >> 1][(nf & 1) * 2];
                    mma16(acc[mf][nf], A1[ks][mf], bf);
                    mma16(acc[mf][nf], A2[ks][mf], bf);
                }
            // B2: A1xB2
#pragma unroll
            for (int mf = 0; mf < 2; mf++)
#pragma unroll
                for (int nf = 0; nf < 8; nf++) {
                    const uint32_t* bf = &B2f[ks][nf >> 1][(nf & 1) * 2];
                    mma16(acc[mf][nf], A1[ks][mf], bf);
                }
        }

        // ---- grouped drain every 4 chunks (128 K) ----
        if ((c & 3) == 3) {
#pragma unroll
            for (int mf = 0; mf < 2; mf++)
#pragma unroll
                for (int nf = 0; nf < 8; nf++)
#pragma unroll
                    for (int e = 0; e < 4; e++) {
                        msum[mf][nf][e] += acc[mf][nf][e];
                        acc[mf][nf][e] = 0.f;
                    }
        }

        if (more) {
            uint32_t p1[8], p2[8];
            const float* xs = reinterpret_cast<const float*>(x);
#pragma unroll
            for (int j = 0; j < 8; j++)
                hsplit2(xs[2 * j], xs[2 * j + 1], p1[j], p2[j]);
            uint4* d1 = reinterpret_cast<uint4*>(
                &S[nst * STG_W + A_S(0) + rA * RW + hA * 8]);
            uint4* d2 = reinterpret_cast<uint4*>(
                &S[nst * STG_W + A_S(1) + rA * RW + hA * 8]);
            d1[0] = make_uint4(p1[0], p1[1], p1[2], p1[3]);
            d1[1] = make_uint4(p1[4], p1[5], p1[6], p1[7]);
            d2[0] = make_uint4(p2[0], p2[1], p2[2], p2[3]);
            d2[1] = make_uint4(p2[4], p2[5], p2[6], p2[7]);
            asm volatile("cp.async.wait_group 0;" ::: "memory");
        }
        __syncthreads();
    }

    // ---- epilogue: relu(x+bias)*lin_w, reduce over this CTA's 128 co ----
    float bias_v[8][2], lw_v[8][2];
#pragma unroll
    for (int nf = 0; nf < 8; nf++)
#pragma unroll
        for (int e = 0; e < 2; e++) {
            int cg = co0 + wn * 64 + nf * 8 + 2 * q + e;
            bias_v[nf][e] = convb[cg];
            lw_v[nf][e]   = linw[cg];
        }
    float* red = S;
#pragma unroll
    for (int mf = 0; mf < 2; mf++) {
#pragma unroll
        for (int h = 0; h < 2; h++) {
            float s = 0.f;
#pragma unroll
            for (int nf = 0; nf < 8; nf++)
#pragma unroll
                for (int e = 0; e < 2; e++) {
                    float xv = msum[mf][nf][h * 2 + e] + bias_v[nf][e];
                    xv = fmaxf(xv, 0.f);
                    s = fmaf(lw_v[nf][e], xv, s);
                }
            s += __shfl_xor_sync(0xffffffffu, s, 1);
            s += __shfl_xor_sync(0xffffffffu, s, 2);
            if (q == 0)
                red[wn * 128 + wm * 32 + mf * 16 + h * 8 + g] = s;
        }
    }
    __syncthreads();
    if (tid < 128) {
        float v = red[tid] + red[128 + tid];
        int t = tt0 + tid;
        if (t < Tn) g_part[cb * BTn + b * Tn + t] = v;
    }
}

// ---------------- 2) alpha = sigmoid(fp64 sum of 4 partials + lin_b) --------
__global__ void alpha_k(const float* __restrict__ linb) {
    int idx = blockIdx.x * blockDim.x + threadIdx.x;
    if (idx >= BTn) return;
    double l = (double)linb[0];
#pragma unroll
    for (int p = 0; p < NB; p++) l += (double)g_part[p * BTn + idx];
    float lf = (float)l;
    g_alpha[idx] = 1.0f / (1.0f + expf(-lf));
}

// ---------------- 3) loss ----------------------------------------------------
__global__ void loss_a_k() {
    int b = blockIdx.x;
    __shared__ float sm[256];
    float s = 0.f;
    for (int t = threadIdx.x; t < Tn; t += 256) s += g_alpha[b * Tn + t];
    sm[threadIdx.x] = s;
    __syncthreads();
    for (int st = 128; st > 0; st >>= 1) {
        if (threadIdx.x < st) sm[threadIdx.x] += sm[threadIdx.x + st];
        __syncthreads();
    }
    if (threadIdx.x == 0) g_bsum[b] = sm[0];
}
__global__ void loss_b_k(float* out, int out_size) {
    if ((long long)out_size > LOSS_OFF) {
        float s = 0.f;
        for (int b = 0; b < Bn; b++) s += fabsf(g_bsum[b]);
        out[LOSS_OFF] = s;
    }
}

// ---------------- 4) scalar CIF scan (one warp per sequence) ----------------
__global__ void scan_k(const int* __restrict__ msk) {
    int b = blockIdx.x;
    int lane = threadIdx.x;
    float acc = 0.0f;
    int nfire = 0;
    for (int t0 = 0; t0 < Tn; t0 += 32) {
        int t = t0 + lane;
        float a = 0.f;
        if (t < Tn) {
            a = g_alpha[b * Tn + t];
            if (msk[b * Tn + t] == 0) a = 0.f;
        }
        int n = min(32, Tn - t0);
        float w1 = 0.f, w2 = 0.f;
        for (int i = 0; i < n; i++) {
            float ai = __shfl_sync(0xffffffffu, a, i);
            float acc2 = acc + ai;
            bool fired = (acc2 >= 1.0f);
            float a1 = 1.0f - acc;
            if (lane == i) {
                if (fired) { w1 = a1; w2 = ai - a1; }
                else       { w1 = ai; w2 = 0.f; }
            }
            if (fired) {
                if (lane == i) g_fpos[b * Tn + nfire] = t0 + i;
                nfire++;
                acc = ai - a1;
            } else {
                acc = acc2;
            }
        }
        if (t < Tn) { g_w1[b * Tn + t] = w1; g_w2[b * Tn + t] = w2; }
    }
    if (lane == 0) {
        g_nfire[b] = nfire;
        g_tail[b]  = (acc >= 0.5f) ? 1 : 0;
    }
}

// ---------------- 5) parallel emission ---------------------------------------
__global__ void emit_k(const float* __restrict__ hs, float* __restrict__ out,
                       int out_size) {
    int row = blockIdx.x;
    int b = row / Tn;
    int j = row % Tn;
    int nf = g_nfire[b];
    int nr = nf + g_tail[b];
    float4 accv = make_float4(0.f, 0.f, 0.f, 0.f);
    int c4 = threadIdx.x;
    const float4* hb = reinterpret_cast<const float4*>(hs) + (size_t)b * Tn * 128;
    if (j < nr) {
        int s = (j == 0) ? 0 : g_fpos[b * Tn + j - 1];
        int e = (j < nf) ? g_fpos[b * Tn + j] : (Tn - 1);
        for (int t = s; t <= e; t++) {
            float w = (t == s && j > 0) ? g_w2[b * Tn + t] : g_w1[b * Tn + t];
            float4 h = hb[(size_t)t * 128 + c4];
            accv.x = fmaf(w, h.x, accv.x);
            accv.y = fmaf(w, h.y, accv.y);
            accv.z = fmaf(w, h.z, accv.z);
            accv.w = fmaf(w, h.w, accv.w);
        }
    }
    reinterpret_cast<float4*>(out)[(size_t)row * 128 + c4] = accv;

    int nz = (accv.x != 0.f) | (accv.y != 0.f) | (accv.z != 0.f) | (accv.w != 0.f);
    __shared__ int s_any[4];
    unsigned bal = __ballot_sync(0xffffffffu, nz);
    if ((threadIdx.x & 31) == 0) s_any[threadIdx.x >> 5] = (bal != 0u);
    __syncthreads();
    if (threadIdx.x == 0) {
        int any = s_any[0] | s_any[1] | s_any[2] | s_any[3];
        if ((long long)out_size >= (long long)MASK_OFF + BTn)
            out[MASK_OFF + row] = any ? 1.0f : 0.0f;
    }
}

// ---------------- launcher ----------------------------------------------------
extern "C" void kernel_launch(void* const* d_in, const int* in_sizes, int n_in,
                              void* d_out, int out_size) {
    const float* hs  = (const float*)d_in[0];
    const int*   msk = (const int*)  d_in[1];
    const float* cw  = (const float*)d_in[2];
    const float* cb  = (const float*)d_in[3];
    const float* lw  = (const float*)d_in[4];
    const float* lb  = (const float*)d_in[5];
    float* out = (float*)d_out;

    cudaFuncSetAttribute(conv_mma_k, cudaFuncAttributeMaxDynamicSharedMemorySize,
                         SMEM_BYTES);

    prep_w_k<<<(Cn * 256 + 255) / 256, 256>>>(cw);
    dummy1_k<<<1, 32>>>();
    dummy2_k<<<1, 32>>>();
    conv_mma_k<<<dim3(NB, 768), 256, SMEM_BYTES>>>(hs, cb, lw);
    alpha_k<<<(BTn + 255) / 256, 256>>>(lb);
    loss_a_k<<<Bn, 256>>>();
    loss_b_k<<<1, 1>>>(out, out_size);
    scan_k<<<Bn, 32>>>(msk);
    emit_k<<<BTn, 128>>>(hs, out, out_size);
}

// round 16
// speedup vs baseline: 1.3268x; 1.0627x over previous
#include <cuda_runtime.h>
#include <cuda_fp16.h>
#include <cstdint>

// ---------------- problem constants ----------------
#define Bn   32
#define Tn   3000
#define Cn   512
#define KKn  2560                 // Cin * ksize
#define KP   (KKn/2)              // packed fp16-pair words per co
#define BTn  (Bn*Tn)              // 96000
#define CS_SZ   (BTn*Cn)
#define MASK_OFF CS_SZ
#define LOSS_OFF (CS_SZ + BTn)

#define NB 8                      // co blocks of 64
#define NCH 80                    // K-chunks of 32
#define RW 20                     // words per smem row (16 data + 4 pad)
// stage (words): A1[128][20]@0, A2@2560, B1[64][20]@5120, B2@6400
#define A_S(s) ((s)*2560)
#define B_S(s) (5120 + (s)*1280)
#define STG_W 7680
#define SMEM_BYTES (2*STG_W*4)    // 61440

// ---------------- scratch ----------------
__device__ uint32_t g_wh1[(size_t)Cn*KP];
__device__ uint32_t g_wh2[(size_t)Cn*KP];
__device__ float g_part[NB*BTn];
__device__ float g_alpha[BTn];
__device__ float g_w1[BTn];
__device__ float g_w2[BTn];
__device__ int   g_fpos[BTn];
__device__ int   g_nfire[Bn];
__device__ int   g_tail[Bn];
__device__ float g_bsum[Bn];

// ---------------- helpers ----------------
__device__ __forceinline__ uint32_t smem_u32(const void* p) {
    uint32_t a;
    asm("{ .reg .u64 t; cvta.to.shared.u64 t, %1; cvt.u32.u64 %0, t; }"
        : "=r"(a) : "l"(p));
    return a;
}
__device__ __forceinline__ void cp16(uint32_t dst, const void* src) {
    asm volatile("cp.async.cg.shared.global [%0], [%1], 16;"
                 :: "r"(dst), "l"(src));
}
__device__ __forceinline__ void mma16(float* c, const uint32_t* a,
                                      const uint32_t* b) {
    asm volatile(
        "mma.sync.aligned.m16n8k16.row.col.f32.f16.f16.f32 "
        "{%0,%1,%2,%3}, {%4,%5,%6,%7}, {%8,%9}, {%0,%1,%2,%3};"
        : "+f"(c[0]), "+f"(c[1]), "+f"(c[2]), "+f"(c[3])
        : "r"(a[0]), "r"(a[1]), "r"(a[2]), "r"(a[3]), "r"(b[0]), "r"(b[1]));
}
__device__ __forceinline__ void ldsm4(uint32_t* r, uint32_t addr) {
    asm volatile("ldmatrix.sync.aligned.m8n8.x4.shared.b16 {%0,%1,%2,%3}, [%4];"
                 : "=r"(r[0]), "=r"(r[1]), "=r"(r[2]), "=r"(r[3])
                 : "r"(addr));
}
// 2-way fp16 split of a float pair (even in low half).
__device__ __forceinline__ void hsplit2(float xe, float xo, uint32_t& P1,
                                        uint32_t& P2) {
    __half2 h1 = __floats2half2_rn(xe, xo);
    float2 b = __half22float2(h1);
    __half2 h2 = __floats2half2_rn(xe - b.x, xo - b.y);
    P1 = *reinterpret_cast<uint32_t*>(&h1);
    P2 = *reinterpret_cast<uint32_t*>(&h2);
}

// ---------------- 0) weights -> 2 packed fp16 planes, K reordered -----------
__global__ void prep_w_k(const float* __restrict__ cw) {
    int idx = blockIdx.x * blockDim.x + threadIdx.x;
    if (idx >= Cn * 256) return;
    int co = idx >> 8;
    int cp = idx & 255;
    const float* p = cw + (size_t)co * KKn + cp * 10;
#pragma unroll
    for (int kr = 0; kr < 5; kr++) {
        uint32_t P1, P2;
        hsplit2(p[kr], p[5 + kr], P1, P2);
        size_t o = (size_t)co * KP + kr * 256 + cp;
        g_wh1[o] = P1;
        g_wh2[o] = P2;
    }
}

// ---------------- dummies (position conv at profiled launch index) ----------
__global__ void dummy1_k() { if (threadIdx.x < Bn) g_bsum[threadIdx.x] = 0.f; }
__global__ void dummy2_k() {}

// ---------------- 1) conv GEMM: fp16 3-term split, 2 CTAs/SM, 128t x 64co ---
// 8 warps: wm=wid&3 (32 t), wn=wid>>2 in {0,1} (32 co each).
__global__ void __launch_bounds__(256, 2)
conv_mma_k(const float* __restrict__ hs, const float* __restrict__ convb,
           const float* __restrict__ linw) {
    extern __shared__ float S[];
    const int tid  = threadIdx.x;
    const int wid  = tid >> 5, lane = tid & 31;
    const int g    = lane >> 2, q = lane & 3;
    const int wm   = wid & 3,  wn = wid >> 2;
    const int cb   = blockIdx.x;
    const int tile = blockIdx.y;
    const int b    = tile / 24;
    const int tt0  = (tile % 24) * 128;
    const int co0  = cb * 64;
    const uint32_t sm0 = smem_u32(S);

    // fill roles: A 2 threads/row (8 floats each); B 4 threads/row (4 words)
    const int rA  = tid >> 1, hA = tid & 1;
    const int rB  = tid >> 2, qB = (tid & 3) * 4;
    const uint32_t* wsrc1 = g_wh1 + (size_t)(co0 + rB) * KP + qB;
    const uint32_t* wsrc2 = g_wh2 + (size_t)(co0 + rB) * KP + qB;

    // ldmatrix per-lane base addresses (bytes)
    const uint32_t aRow = wm * 32 + (lane & 7) + ((lane >> 3) & 1) * 8;
    const uint32_t aWord = (lane >> 4) * 4;
    const uint32_t bRow = wn * 32 + (lane & 7) + (lane >> 4) * 8;
    const uint32_t bWord = ((lane >> 3) & 1) * 4;
    const uint32_t aBase = sm0 + (A_S(0) + aRow * RW + aWord) * 4;
    const uint32_t bBase = sm0 + (B_S(0) + bRow * RW + bWord) * 4;

    float acc[2][4][4];
    float msum[2][4][4];
#pragma unroll
    for (int i = 0; i < 2; i++)
#pragma unroll
        for (int j = 0; j < 4; j++)
#pragma unroll
            for (int e = 0; e < 4; e++) { acc[i][j][e] = 0.f; msum[i][j][e] = 0.f; }

    // ---- prime stage 0 ----
    {
        cp16(sm0 + (B_S(0) + rB * RW + qB) * 4, wsrc1);
        cp16(sm0 + (B_S(1) - STG_W + STG_W + rB * RW + qB) * 4, wsrc2); // B2 plane
        asm volatile("cp.async.commit_group;" ::: "memory");

        int tsrc = tt0 + rA - 2;
        bool v = ((unsigned)tsrc < (unsigned)Tn);
        const float* src = hs + ((size_t)b * Tn + tsrc) * Cn + hA * 16;
        float4 x[4];
#pragma unroll
        for (int j = 0; j < 4; j++)
            x[j] = v ? reinterpret_cast<const float4*>(src)[j]
                     : make_float4(0.f, 0.f, 0.f, 0.f);
        uint32_t p1[8], p2[8];
        const float* xs = reinterpret_cast<const float*>(x);
#pragma unroll
        for (int j = 0; j < 8; j++)
            hsplit2(xs[2 * j], xs[2 * j + 1], p1[j], p2[j]);
        uint4* d1 = reinterpret_cast<uint4*>(&S[A_S(0) + rA * RW + hA * 8]);
        uint4* d2 = reinterpret_cast<uint4*>(&S[A_S(1) + rA * RW + hA * 8]);
        d1[0] = make_uint4(p1[0], p1[1], p1[2], p1[3]);
        d1[1] = make_uint4(p1[4], p1[5], p1[6], p1[7]);
        d2[0] = make_uint4(p2[0], p2[1], p2[2], p2[3]);
        d2[1] = make_uint4(p2[4], p2[5], p2[6], p2[7]);
        asm volatile("cp.async.wait_group 0;" ::: "memory");
    }
    __syncthreads();

    for (int c = 0; c < NCH; c++) {
        const int st  = c & 1;
        const int nst = st ^ 1;
        const bool more = (c + 1 < NCH);

        float4 x[4];
        if (more) {
            const int kb1 = (c + 1) * 32;
            const int kw1 = kb1 >> 1;
            const uint32_t base = sm0 + nst * STG_W * 4;
            cp16(base + (B_S(0) + rB * RW + qB) * 4, wsrc1 + kw1);
            cp16(base + (B_S(1) - STG_W * nst + STG_W * nst + rB * RW + qB) * 4,
                 wsrc2 + kw1);
            asm volatile("cp.async.commit_group;" ::: "memory");
            const int kr = kb1 >> 9, ci = kb1 & 511;
            int tsrc = tt0 + rA + kr - 2;
            bool v = ((unsigned)tsrc < (unsigned)Tn);
            const float* src = hs + ((size_t)b * Tn + tsrc) * Cn + ci + hA * 16;
#pragma unroll
            for (int j = 0; j < 4; j++)
                x[j] = v ? reinterpret_cast<const float4*>(src)[j]
                         : make_float4(0.f, 0.f, 0.f, 0.f);
        }

        // ---- compute: 3 split terms, 2 k-steps of K=16 ----
        const uint32_t stoff = (uint32_t)st * STG_W * 4;
#pragma unroll
        for (int ks = 0; ks < 2; ks++) {
            const uint32_t kso = ks * 32;
            uint32_t A1[2][4], A2[2][4];
#pragma unroll
            for (int mf = 0; mf < 2; mf++) {
                ldsm4(A1[mf], aBase + stoff + mf * (16 * RW * 4) + kso);
                ldsm4(A2[mf], aBase + stoff + 2560 * 4 + mf * (16 * RW * 4) + kso);
            }
            uint32_t B1f[2][4];
#pragma unroll
            for (int nfp = 0; nfp < 2; nfp++)
                ldsm4(B1f[nfp], bBase + stoff + nfp * (16 * RW * 4) + kso);
#pragma unroll
            for (int mf = 0; mf < 2; mf++)
#pragma unroll
                for (int nf = 0; nf < 4; nf++) {
                    const uint32_t* bf = &B1f[nf >> 1][(nf & 1) * 2];
                    mma16(acc[mf][nf], A1[mf], bf);
                    mma16(acc[mf][nf], A2[mf], bf);
                }
            uint32_t B2f[2][4];
#pragma unroll
            for (int nfp = 0; nfp < 2; nfp++)
                ldsm4(B2f[nfp], bBase + stoff + 1280 * 4 + nfp * (16 * RW * 4) + kso);
#pragma unroll
            for (int mf = 0; mf < 2; mf++)
#pragma unroll
                for (int nf = 0; nf < 4; nf++) {
                    const uint32_t* bf = &B2f[nf >> 1][(nf & 1) * 2];
                    mma16(acc[mf][nf], A1[mf], bf);
                }
        }

        // ---- grouped drain every 4 chunks (128 K) ----
        if ((c & 3) == 3) {
#pragma unroll
            for (int mf = 0; mf < 2; mf++)
#pragma unroll
                for (int nf = 0; nf < 4; nf++)
#pragma unroll
                    for (int e = 0; e < 4; e++) {
                        msum[mf][nf][e] += acc[mf][nf][e];
                        acc[mf][nf][e] = 0.f;
                    }
        }

        if (more) {
            uint32_t p1[8], p2[8];
            const float* xs = reinterpret_cast<const float*>(x);
#pragma unroll
            for (int j = 0; j < 8; j++)
                hsplit2(xs[2 * j], xs[2 * j + 1], p1[j], p2[j]);
            uint4* d1 = reinterpret_cast<uint4*>(
                &S[nst * STG_W + A_S(0) + rA * RW + hA * 8]);
            uint4* d2 = reinterpret_cast<uint4*>(
                &S[nst * STG_W + A_S(1) + rA * RW + hA * 8]);
            d1[0] = make_uint4(p1[0], p1[1], p1[2], p1[3]);
            d1[1] = make_uint4(p1[4], p1[5], p1[6], p1[7]);
            d2[0] = make_uint4(p2[0], p2[1], p2[2], p2[3]);
            d2[1] = make_uint4(p2[4], p2[5], p2[6], p2[7]);
            asm volatile("cp.async.wait_group 0;" ::: "memory");
        }
        __syncthreads();
    }

    // ---- epilogue: relu(x+bias)*lin_w, reduce over this CTA's 64 co ----
    float bias_v[4][2], lw_v[4][2];
#pragma unroll
    for (int nf = 0; nf < 4; nf++)
#pragma unroll
        for (int e = 0; e < 2; e++) {
            int cg = co0 + wn * 32 + nf * 8 + 2 * q + e;
            bias_v[nf][e] = convb[cg];
            lw_v[nf][e]   = linw[cg];
        }
    float* red = S;
#pragma unroll
    for (int mf = 0; mf < 2; mf++) {
#pragma unroll
        for (int h = 0; h < 2; h++) {
            float s = 0.f;
#pragma unroll
            for (int nf = 0; nf < 4; nf++)
#pragma unroll
                for (int e = 0; e < 2; e++) {
                    float xv = msum[mf][nf][h * 2 + e] + bias_v[nf][e];
                    xv = fmaxf(xv, 0.f);
                    s = fmaf(lw_v[nf][e], xv, s);
                }
            s += __shfl_xor_sync(0xffffffffu, s, 1);
            s += __shfl_xor_sync(0xffffffffu, s, 2);
            if (q == 0)
                red[wn * 128 + wm * 32 + mf * 16 + h * 8 + g] = s;
        }
    }
    __syncthreads();
    if (tid < 128) {
        float v = red[tid] + red[128 + tid];
        int t = tt0 + tid;
        if (t < Tn) g_part[cb * BTn + b * Tn + t] = v;
    }
}

// ---------------- 2) alpha = sigmoid(fp64 sum of 8 partials + lin_b) --------
__global__ void alpha_k(const float* __restrict__ linb) {
    int idx = blockIdx.x * blockDim.x + threadIdx.x;
    if (idx >= BTn) return;
    double l = (double)linb[0];
#pragma unroll
    for (int p = 0; p < NB; p++) l += (double)g_part[p * BTn + idx];
    float lf = (float)l;
    g_alpha[idx] = 1.0f / (1.0f + expf(-lf));
}

// ---------------- 3) loss ----------------------------------------------------
__global__ void loss_a_k() {
    int b = blockIdx.x;
    __shared__ float sm[256];
    float s = 0.f;
    for (int t = threadIdx.x; t < Tn; t += 256) s += g_alpha[b * Tn + t];
    sm[threadIdx.x] = s;
    __syncthreads();
    for (int st = 128; st > 0; st >>= 1) {
        if (threadIdx.x < st) sm[threadIdx.x] += sm[threadIdx.x + st];
        __syncthreads();
    }
    if (threadIdx.x == 0) g_bsum[b] = sm[0];
}
__global__ void loss_b_k(float* out, int out_size) {
    if ((long long)out_size > LOSS_OFF) {
        float s = 0.f;
        for (int b = 0; b < Bn; b++) s += fabsf(g_bsum[b]);
        out[LOSS_OFF] = s;
    }
}

// ---------------- 4) scalar CIF scan (one warp per sequence) ----------------
__global__ void scan_k(const int* __restrict__ msk) {
    int b = blockIdx.x;
    int lane = threadIdx.x;
    float acc = 0.0f;
    int nfire = 0;
    for (int t0 = 0; t0 < Tn; t0 += 32) {
        int t = t0 + lane;
        float a = 0.f;
        if (t < Tn) {
            a = g_alpha[b * Tn + t];
            if (msk[b * Tn + t] == 0) a = 0.f;
        }
        int n = min(32, Tn - t0);
        float w1 = 0.f, w2 = 0.f;
        for (int i = 0; i < n; i++) {
            float ai = __shfl_sync(0xffffffffu, a, i);
            float acc2 = acc + ai;
            bool fired = (acc2 >= 1.0f);
            float a1 = 1.0f - acc;
            if (lane == i) {
                if (fired) { w1 = a1; w2 = ai - a1; }
                else       { w1 = ai; w2 = 0.f; }
            }
            if (fired) {
                if (lane == i) g_fpos[b * Tn + nfire] = t0 + i;
                nfire++;
                acc = ai - a1;
            } else {
                acc = acc2;
            }
        }
        if (t < Tn) { g_w1[b * Tn + t] = w1; g_w2[b * Tn + t] = w2; }
    }
    if (lane == 0) {
        g_nfire[b] = nfire;
        g_tail[b]  = (acc >= 0.5f) ? 1 : 0;
    }
}

// ---------------- 5) parallel emission ---------------------------------------
__global__ void emit_k(const float* __restrict__ hs, float* __restrict__ out,
                       int out_size) {
    int row = blockIdx.x;
    int b = row / Tn;
    int j = row % Tn;
    int nf = g_nfire[b];
    int nr = nf + g_tail[b];
    float4 accv = make_float4(0.f, 0.f, 0.f, 0.f);
    int c4 = threadIdx.x;
    const float4* hb = reinterpret_cast<const float4*>(hs) + (size_t)b * Tn * 128;
    if (j < nr) {
        int s = (j == 0) ? 0 : g_fpos[b * Tn + j - 1];
        int e = (j < nf) ? g_fpos[b * Tn + j] : (Tn - 1);
        for (int t = s; t <= e; t++) {
            float w = (t == s && j > 0) ? g_w2[b * Tn + t] : g_w1[b * Tn + t];
            float4 h = hb[(size_t)t * 128 + c4];
            accv.x = fmaf(w, h.x, accv.x);
            accv.y = fmaf(w, h.y, accv.y);
            accv.z = fmaf(w, h.z, accv.z);
            accv.w = fmaf(w, h.w, accv.w);
        }
    }
    reinterpret_cast<float4*>(out)[(size_t)row * 128 + c4] = accv;

    int nz = (accv.x != 0.f) | (accv.y != 0.f) | (accv.z != 0.f) | (accv.w != 0.f);
    __shared__ int s_any[4];
    unsigned bal = __ballot_sync(0xffffffffu, nz);
    if ((threadIdx.x & 31) == 0) s_any[threadIdx.x >> 5] = (bal != 0u);
    __syncthreads();
    if (threadIdx.x == 0) {
        int any = s_any[0] | s_any[1] | s_any[2] | s_any[3];
        if ((long long)out_size >= (long long)MASK_OFF + BTn)
            out[MASK_OFF + row] = any ? 1.0f : 0.0f;
    }
}

// ---------------- launcher ----------------------------------------------------
extern "C" void kernel_launch(void* const* d_in, const int* in_sizes, int n_in,
                              void* d_out, int out_size) {
    const float* hs  = (const float*)d_in[0];
    const int*   msk = (const int*)  d_in[1];
    const float* cw  = (const float*)d_in[2];
    const float* cb  = (const float*)d_in[3];
    const float* lw  = (const float*)d_in[4];
    const float* lb  = (const float*)d_in[5];
    float* out = (float*)d_out;

    cudaFuncSetAttribute(conv_mma_k, cudaFuncAttributeMaxDynamicSharedMemorySize,
                         SMEM_BYTES);

    prep_w_k<<<(Cn * 256 + 255) / 256, 256>>>(cw);
    dummy1_k<<<1, 32>>>();
    dummy2_k<<<1, 32>>>();
    conv_mma_k<<<dim3(NB, 768), 256, SMEM_BYTES>>>(hs, cb, lw);
    alpha_k<<<(BTn + 255) / 256, 256>>>(lb);
    loss_a_k<<<Bn, 256>>>();
    loss_b_k<<<1, 1>>>(out, out_size);
    scan_k<<<Bn, 32>>>(msk);
    emit_k<<<BTn, 128>>>(hs, out, out_size);
}